// round 13
// baseline (speedup 1.0000x reference)
#include <cuda_runtime.h>
#include <cuda_fp16.h>
#include <cstdint>

#define NF 32
#define DIM 64
#define NPAIR 496
#define BATCH 2048
#define TILE_M 128
#define LDSTR 72                      // fp16 elems per smem row (64 + 8 pad)
#define OSTR 72                       // floats per bounce row (72 is the validated winner)

// smem layout: A [0, 18432), W [18432, 27648); bounce aliases [0, 36864)
#define SM_A 0
#define SM_W 18432
#define SM_TOTAL 36864

#define FE4 (BATCH * NF * DIM / 4)    // 1048576 float4 in fe

// ---- global fp16 scratch (pre-converted) ----
__device__ __align__(16) __half g_feF[BATCH * NF * DIM];
__device__ __align__(16) __half g_WF[NPAIR * DIM * DIM];

__device__ __forceinline__ uint32_t s2u(const void* p) {
    uint32_t a;
    asm("{ .reg .u64 t; cvta.to.shared.u64 t, %1; cvt.u32.u64 %0, t; }" : "=r"(a) : "l"(p));
    return a;
}
__device__ __forceinline__ void cpasync16(uint32_t s, const void* g) {
    asm volatile("{ .reg .u64 gp; cvta.to.global.u64 gp, %1; "
                 "cp.async.ca.shared.global [%0], [gp], 16; }"
                 :: "r"(s), "l"(g) : "memory");
}
__device__ __forceinline__ void ldsm_x4(uint32_t* r, uint32_t a) {
    asm volatile("ldmatrix.sync.aligned.m8n8.x4.shared.b16 {%0,%1,%2,%3}, [%4];"
                 : "=r"(r[0]), "=r"(r[1]), "=r"(r[2]), "=r"(r[3]) : "r"(a));
}
__device__ __forceinline__ void ldsm_x4t(uint32_t* r, uint32_t a) {
    asm volatile("ldmatrix.sync.aligned.m8n8.x4.trans.shared.b16 {%0,%1,%2,%3}, [%4];"
                 : "=r"(r[0]), "=r"(r[1]), "=r"(r[2]), "=r"(r[3]) : "r"(a));
}
__device__ __forceinline__ void mma_f16(float* d, const uint32_t* a, const uint32_t* b) {
    asm volatile("mma.sync.aligned.m16n8k16.row.col.f32.f16.f16.f32 "
                 "{%0,%1,%2,%3}, {%4,%5,%6,%7}, {%8,%9}, {%0,%1,%2,%3};"
                 : "+f"(d[0]), "+f"(d[1]), "+f"(d[2]), "+f"(d[3])
                 : "r"(a[0]), "r"(a[1]), "r"(a[2]), "r"(a[3]), "r"(b[0]), "r"(b[1]));
}

// ---- fused prep kernel: fp32 -> fp16 ----
__global__ __launch_bounds__(256) void cvt_all_kernel(
    const float* __restrict__ fe, const float* __restrict__ W) {
    int idx = blockIdx.x * 256 + threadIdx.x;
    float4 v;
    __half2* dst;
    if (idx < FE4) {
        v = reinterpret_cast<const float4*>(fe)[idx];
        dst = reinterpret_cast<__half2*>(g_feF) + idx * 2;
    } else {
        v = reinterpret_cast<const float4*>(W)[idx - FE4];
        dst = reinterpret_cast<__half2*>(g_WF) + (idx - FE4) * 2;
    }
    dst[0] = __floats2half2_rn(v.x, v.y);
    dst[1] = __floats2half2_rn(v.z, v.w);
}

// out[b, p, e] = (sum_d fe[b, i(p), d] * W[p, d, e]) * fe[b, j(p), e]
__global__ __launch_bounds__(256, 4) void bilinear_mma_kernel(
    const float* __restrict__ fe,   // fp32, for v_j epilogue
    float* __restrict__ out)
{
    extern __shared__ char smem[];
    const uint32_t base = s2u(smem);
    const int tid   = threadIdx.x;      // 0..255
    const int wid   = tid >> 5;
    const int lid   = tid & 31;
    const int p     = blockIdx.y;       // pair 0..495
    const int btile = blockIdx.x;

    // decode (i, j) from triu_indices(NF, k=1)
    int i = 0, rem = p;
    while (rem >= NF - 1 - i) { rem -= NF - 1 - i; ++i; }
    const int j = i + 1 + rem;

    // ---- async loads (fp16) ----
    // W: 64 rows x 64 fp16 = 512 x 16B chunks, 2/thread
    {
        #pragma unroll
        for (int q = 0; q < 2; ++q) {
            int chunk = tid + 256 * q;                    // 0..511
            int row = chunk >> 3, c = chunk & 7;
            const size_t gb = (size_t)p * DIM * DIM + row * DIM + c * 8;
            cpasync16(base + SM_W + (uint32_t)(row * (LDSTR * 2) + c * 16), g_WF + gb);
        }
    }
    // A: 128 rows x 64 fp16 = 1024 chunks, 4/thread
    {
        #pragma unroll
        for (int q = 0; q < 4; ++q) {
            int chunk = tid + 256 * q;                    // 0..1023
            int row = chunk >> 3, c = chunk & 7;
            const size_t gb = ((size_t)(btile * TILE_M + row) * NF + i) * DIM + c * 8;
            cpasync16(base + SM_A + (uint32_t)(row * (LDSTR * 2) + c * 16), g_feF + gb);
        }
    }
    asm volatile("cp.async.commit_group;" ::: "memory");
    asm volatile("cp.async.wait_group 0;" ::: "memory");
    __syncthreads();

    // ---- warp tile: 32 (m) x 32 (n); 4x2 warp grid (R4 schedule) ----
    const int MR = (wid & 3) * 32;
    const int NC = (wid >> 2) * 32;
    const int lr = lid & 15, lc = lid >> 4;

    const uint32_t aA0 = base + SM_A + (uint32_t)(MR + lr) * (LDSTR * 2) + lc * 16;
    const uint32_t aA1 = aA0 + 16 * (LDSTR * 2);
    const uint32_t aW  = base + SM_W + (uint32_t)lr * (LDSTR * 2) + NC * 2 + lc * 16;

    float acc[2][4][4] = {};

    #pragma unroll
    for (int ks = 0; ks < 4; ++ks) {
        const uint32_t kA = (uint32_t)(ks * 32);               // +16 k-cols (bytes)
        const uint32_t kB = (uint32_t)(ks * 16 * (LDSTR * 2)); // +16 k-rows (bytes)

        uint32_t af[2][4], wf[8];
        ldsm_x4(af[0], aA0 + kA);
        ldsm_x4(af[1], aA1 + kA);
        ldsm_x4t(wf,     aW + kB);
        ldsm_x4t(wf + 4, aW + kB + 32);

        #pragma unroll
        for (int mi = 0; mi < 2; ++mi)
            #pragma unroll
            for (int ni = 0; ni < 4; ++ni)
                mma_f16(acc[mi][ni], af[mi], &wf[ni * 2]);
    }

    // ---- epilogue: smem bounce -> coalesced vj-scale + store ----
    __syncthreads();   // all LDSM reads done; smem becomes bounce buffer
    float* bounce = reinterpret_cast<float*>(smem);

    const int r  = lid >> 2;
    const int cp = (lid & 3) * 2;
    #pragma unroll
    for (int mi = 0; mi < 2; ++mi)
        #pragma unroll
        for (int h = 0; h < 2; ++h) {
            const int row = MR + mi * 16 + h * 8 + r;
            #pragma unroll
            for (int ni = 0; ni < 4; ++ni) {
                const int col = NC + ni * 8 + cp;
                *reinterpret_cast<float2*>(bounce + row * OSTR + col) =
                    make_float2(acc[mi][ni][h * 2 + 0], acc[mi][ni][h * 2 + 1]);
            }
        }
    __syncthreads();

    const int lane8 = tid & 7;
    #pragma unroll
    for (int rr = 0; rr < 4; ++rr) {
        const int row = rr * 32 + (tid >> 3);
        const int b = btile * TILE_M + row;
        const float* vjr = fe + ((size_t)b * NF + j) * DIM;
        float* orow = out + ((size_t)b * NPAIR + p) * DIM;
        #pragma unroll
        for (int h = 0; h < 2; ++h) {
            const int col = lane8 * 4 + 32 * h;
            float4 a4 = *reinterpret_cast<const float4*>(bounce + row * OSTR + col);
            float4 vj = *reinterpret_cast<const float4*>(vjr + col);
            float4 o;
            o.x = a4.x * vj.x; o.y = a4.y * vj.y;
            o.z = a4.z * vj.z; o.w = a4.w * vj.w;
            *reinterpret_cast<float4*>(orow + col) = o;
        }
    }
}

extern "C" void kernel_launch(void* const* d_in, const int* in_sizes, int n_in,
                              void* d_out, int out_size) {
    const float* fe = (const float*)d_in[0];   // feature_emb [2048, 32, 64] fp32
    const float* W  = (const float*)d_in[1];   // bilinear_W [496, 64, 64] fp32
    float* out = (float*)d_out;                // [2048, 496, 64] fp32

    const int n4 = FE4 + NPAIR * DIM * DIM / 4;     // 1556480 float4 total
    cvt_all_kernel<<<(n4 + 255) / 256, 256>>>(fe, W);

    cudaFuncSetAttribute(bilinear_mma_kernel,
                         cudaFuncAttributeMaxDynamicSharedMemorySize, SM_TOTAL);
    dim3 grid(BATCH / TILE_M, NPAIR);          // (16, 496)
    bilinear_mma_kernel<<<grid, 256, SM_TOTAL>>>(fe, out);
}

// round 14
// speedup vs baseline: 1.0976x; 1.0976x over previous
#include <cuda_runtime.h>
#include <cuda_fp16.h>
#include <cstdint>

#define NF 32
#define DIM 64
#define NPAIR 496
#define BATCH 2048
#define TILE_M 128
#define LDSTR 72                      // fp16 elems per smem row (64 + 8 pad)
#define OSTR 72                       // floats per bounce row (validated winner)

// smem layout: A [0, 18432), W [18432, 27648); bounce aliases [0, 36864)
#define SM_A 0
#define SM_W 18432
#define SM_TOTAL 36864

#define FE4 (BATCH * NF * DIM / 4)    // 1048576 float4 in fe

// ---- global fp16 scratch (pre-converted) ----
__device__ __align__(16) __half g_feF[BATCH * NF * DIM];
__device__ __align__(16) __half g_WF[NPAIR * DIM * DIM];

__device__ __forceinline__ uint32_t s2u(const void* p) {
    uint32_t a;
    asm("{ .reg .u64 t; cvta.to.shared.u64 t, %1; cvt.u32.u64 %0, t; }" : "=r"(a) : "l"(p));
    return a;
}
__device__ __forceinline__ void cpasync16(uint32_t s, const void* g) {
    asm volatile("{ .reg .u64 gp; cvta.to.global.u64 gp, %1; "
                 "cp.async.ca.shared.global [%0], [gp], 16; }"
                 :: "r"(s), "l"(g) : "memory");
}
__device__ __forceinline__ void ldsm_x4(uint32_t* r, uint32_t a) {
    asm volatile("ldmatrix.sync.aligned.m8n8.x4.shared.b16 {%0,%1,%2,%3}, [%4];"
                 : "=r"(r[0]), "=r"(r[1]), "=r"(r[2]), "=r"(r[3]) : "r"(a));
}
__device__ __forceinline__ void ldsm_x4t(uint32_t* r, uint32_t a) {
    asm volatile("ldmatrix.sync.aligned.m8n8.x4.trans.shared.b16 {%0,%1,%2,%3}, [%4];"
                 : "=r"(r[0]), "=r"(r[1]), "=r"(r[2]), "=r"(r[3]) : "r"(a));
}
__device__ __forceinline__ void mma_f16(float* d, const uint32_t* a, const uint32_t* b) {
    asm volatile("mma.sync.aligned.m16n8k16.row.col.f32.f16.f16.f32 "
                 "{%0,%1,%2,%3}, {%4,%5,%6,%7}, {%8,%9}, {%0,%1,%2,%3};"
                 : "+f"(d[0]), "+f"(d[1]), "+f"(d[2]), "+f"(d[3])
                 : "r"(a[0]), "r"(a[1]), "r"(a[2]), "r"(a[3]), "r"(b[0]), "r"(b[1]));
}

// ---- fused prep kernel: fp32 -> fp16 ----
__global__ __launch_bounds__(256) void cvt_all_kernel(
    const float* __restrict__ fe, const float* __restrict__ W) {
    int idx = blockIdx.x * 256 + threadIdx.x;
    float4 v;
    __half2* dst;
    if (idx < FE4) {
        v = reinterpret_cast<const float4*>(fe)[idx];
        dst = reinterpret_cast<__half2*>(g_feF) + idx * 2;
    } else {
        v = reinterpret_cast<const float4*>(W)[idx - FE4];
        dst = reinterpret_cast<__half2*>(g_WF) + (idx - FE4) * 2;
    }
    dst[0] = __floats2half2_rn(v.x, v.y);
    dst[1] = __floats2half2_rn(v.z, v.w);
}

// out[b, p, e] = (sum_d fe[b, i(p), d] * W[p, d, e]) * fe[b, j(p), e]
__global__ __launch_bounds__(256, 3) void bilinear_mma_kernel(float* __restrict__ out)
{
    extern __shared__ char smem[];
    const uint32_t base = s2u(smem);
    const int tid   = threadIdx.x;      // 0..255
    const int wid   = tid >> 5;
    const int lid   = tid & 31;
    const int p     = blockIdx.y;       // pair 0..495
    const int btile = blockIdx.x;

    // decode (i, j) from triu_indices(NF, k=1)
    int i = 0, rem = p;
    while (rem >= NF - 1 - i) { rem -= NF - 1 - i; ++i; }
    const int j = i + 1 + rem;

    // ---- async loads (fp16) ----
    // W: 64 rows x 64 fp16 = 512 x 16B chunks, 2/thread
    {
        #pragma unroll
        for (int q = 0; q < 2; ++q) {
            int chunk = tid + 256 * q;                    // 0..511
            int row = chunk >> 3, c = chunk & 7;
            const size_t gb = (size_t)p * DIM * DIM + row * DIM + c * 8;
            cpasync16(base + SM_W + (uint32_t)(row * (LDSTR * 2) + c * 16), g_WF + gb);
        }
    }
    // A: 128 rows x 64 fp16 = 1024 chunks, 4/thread
    {
        #pragma unroll
        for (int q = 0; q < 4; ++q) {
            int chunk = tid + 256 * q;                    // 0..1023
            int row = chunk >> 3, c = chunk & 7;
            const size_t gb = ((size_t)(btile * TILE_M + row) * NF + i) * DIM + c * 8;
            cpasync16(base + SM_A + (uint32_t)(row * (LDSTR * 2) + c * 16), g_feF + gb);
        }
    }
    asm volatile("cp.async.commit_group;" ::: "memory");
    asm volatile("cp.async.wait_group 0;" ::: "memory");
    __syncthreads();

    // ---- warp tile: 32 (m) x 32 (n); 4x2 warp grid (R4 schedule) ----
    const int MR = (wid & 3) * 32;
    const int NC = (wid >> 2) * 32;
    const int lr = lid & 15, lc = lid >> 4;

    const uint32_t aA0 = base + SM_A + (uint32_t)(MR + lr) * (LDSTR * 2) + lc * 16;
    const uint32_t aA1 = aA0 + 16 * (LDSTR * 2);
    const uint32_t aW  = base + SM_W + (uint32_t)lr * (LDSTR * 2) + NC * 2 + lc * 16;

    float acc[2][4][4] = {};

    #pragma unroll
    for (int ks = 0; ks < 4; ++ks) {
        const uint32_t kA = (uint32_t)(ks * 32);               // +16 k-cols (bytes)
        const uint32_t kB = (uint32_t)(ks * 16 * (LDSTR * 2)); // +16 k-rows (bytes)

        uint32_t af[2][4], wf[8];
        ldsm_x4(af[0], aA0 + kA);
        ldsm_x4(af[1], aA1 + kA);
        ldsm_x4t(wf,     aW + kB);
        ldsm_x4t(wf + 4, aW + kB + 32);

        #pragma unroll
        for (int mi = 0; mi < 2; ++mi)
            #pragma unroll
            for (int ni = 0; ni < 4; ++ni)
                mma_f16(acc[mi][ni], af[mi], &wf[ni * 2]);
    }

    // ---- epilogue: smem bounce -> coalesced vj-scale + store ----
    __syncthreads();   // all LDSM reads done; smem becomes bounce buffer
    float* bounce = reinterpret_cast<float*>(smem);

    const int r  = lid >> 2;
    const int cp = (lid & 3) * 2;
    #pragma unroll
    for (int mi = 0; mi < 2; ++mi)
        #pragma unroll
        for (int h = 0; h < 2; ++h) {
            const int row = MR + mi * 16 + h * 8 + r;
            #pragma unroll
            for (int ni = 0; ni < 4; ++ni) {
                const int col = NC + ni * 8 + cp;
                *reinterpret_cast<float2*>(bounce + row * OSTR + col) =
                    make_float2(acc[mi][ni][h * 2 + 0], acc[mi][ni][h * 2 + 1]);
            }
        }
    __syncthreads();

    const int lane8 = tid & 7;
    #pragma unroll
    for (int rr = 0; rr < 4; ++rr) {
        const int row = rr * 32 + (tid >> 3);
        const int b = btile * TILE_M + row;
        const __half* vjr = g_feF + ((size_t)b * NF + j) * DIM;   // fp16 v_j
        float* orow = out + ((size_t)b * NPAIR + p) * DIM;
        #pragma unroll
        for (int h = 0; h < 2; ++h) {
            const int col = lane8 * 4 + 32 * h;
            float4 a4 = *reinterpret_cast<const float4*>(bounce + row * OSTR + col);
            uint2 vraw = *reinterpret_cast<const uint2*>(vjr + col);   // 4 halves
            __half2 v01 = *reinterpret_cast<__half2*>(&vraw.x);
            __half2 v23 = *reinterpret_cast<__half2*>(&vraw.y);
            float2 f01 = __half22float2(v01);
            float2 f23 = __half22float2(v23);
            float4 o;
            o.x = a4.x * f01.x; o.y = a4.y * f01.y;
            o.z = a4.z * f23.x; o.w = a4.w * f23.y;
            *reinterpret_cast<float4*>(orow + col) = o;
        }
    }
}

extern "C" void kernel_launch(void* const* d_in, const int* in_sizes, int n_in,
                              void* d_out, int out_size) {
    const float* fe = (const float*)d_in[0];   // feature_emb [2048, 32, 64] fp32
    const float* W  = (const float*)d_in[1];   // bilinear_W [496, 64, 64] fp32
    float* out = (float*)d_out;                // [2048, 496, 64] fp32

    const int n4 = FE4 + NPAIR * DIM * DIM / 4;     // 1556480 float4 total
    cvt_all_kernel<<<(n4 + 255) / 256, 256>>>(fe, W);

    cudaFuncSetAttribute(bilinear_mma_kernel,
                         cudaFuncAttributeMaxDynamicSharedMemorySize, SM_TOTAL);
    dim3 grid(BATCH / TILE_M, NPAIR);          // (16, 496)
    bilinear_mma_kernel<<<grid, 256, SM_TOTAL>>>(out);
}

// round 15
// speedup vs baseline: 1.1640x; 1.0604x over previous
#include <cuda_runtime.h>
#include <cuda_fp16.h>
#include <cstdint>

#define NF 32
#define DIM 64
#define NPAIR 496
#define BATCH 2048
#define TILE_M 128
#define LDSTR 72                      // fp16 elems per smem row (64 + 8 pad)
#define BSTR 40                       // floats per per-warp bounce row (40 mod 32 = 8 -> conflict-free)

// smem layout: A [0, 18432), W [18432, 27648), per-warp bounce [27648, 68608)
#define SM_A 0
#define SM_W 18432
#define SM_BNC 27648
#define BNC_WARP 5120                 // 32 * 40 * 4 bytes per warp
#define SM_TOTAL 68608

#define FE4 (BATCH * NF * DIM / 4)    // 1048576 float4 in fe

// ---- global fp16 scratch (pre-converted) ----
__device__ __align__(16) __half g_feF[BATCH * NF * DIM];
__device__ __align__(16) __half g_WF[NPAIR * DIM * DIM];

__device__ __forceinline__ uint32_t s2u(const void* p) {
    uint32_t a;
    asm("{ .reg .u64 t; cvta.to.shared.u64 t, %1; cvt.u32.u64 %0, t; }" : "=r"(a) : "l"(p));
    return a;
}
__device__ __forceinline__ void cpasync16(uint32_t s, const void* g) {
    asm volatile("{ .reg .u64 gp; cvta.to.global.u64 gp, %1; "
                 "cp.async.ca.shared.global [%0], [gp], 16; }"
                 :: "r"(s), "l"(g) : "memory");
}
__device__ __forceinline__ void ldsm_x4(uint32_t* r, uint32_t a) {
    asm volatile("ldmatrix.sync.aligned.m8n8.x4.shared.b16 {%0,%1,%2,%3}, [%4];"
                 : "=r"(r[0]), "=r"(r[1]), "=r"(r[2]), "=r"(r[3]) : "r"(a));
}
__device__ __forceinline__ void ldsm_x4t(uint32_t* r, uint32_t a) {
    asm volatile("ldmatrix.sync.aligned.m8n8.x4.trans.shared.b16 {%0,%1,%2,%3}, [%4];"
                 : "=r"(r[0]), "=r"(r[1]), "=r"(r[2]), "=r"(r[3]) : "r"(a));
}
__device__ __forceinline__ void mma_f16(float* d, const uint32_t* a, const uint32_t* b) {
    asm volatile("mma.sync.aligned.m16n8k16.row.col.f32.f16.f16.f32 "
                 "{%0,%1,%2,%3}, {%4,%5,%6,%7}, {%8,%9}, {%0,%1,%2,%3};"
                 : "+f"(d[0]), "+f"(d[1]), "+f"(d[2]), "+f"(d[3])
                 : "r"(a[0]), "r"(a[1]), "r"(a[2]), "r"(a[3]), "r"(b[0]), "r"(b[1]));
}

// ---- fused prep kernel: fp32 -> fp16 ----
__global__ __launch_bounds__(256) void cvt_all_kernel(
    const float* __restrict__ fe, const float* __restrict__ W) {
    int idx = blockIdx.x * 256 + threadIdx.x;
    float4 v;
    __half2* dst;
    if (idx < FE4) {
        v = reinterpret_cast<const float4*>(fe)[idx];
        dst = reinterpret_cast<__half2*>(g_feF) + idx * 2;
    } else {
        v = reinterpret_cast<const float4*>(W)[idx - FE4];
        dst = reinterpret_cast<__half2*>(g_WF) + (idx - FE4) * 2;
    }
    dst[0] = __floats2half2_rn(v.x, v.y);
    dst[1] = __floats2half2_rn(v.z, v.w);
}

// out[b, p, e] = (sum_d fe[b, i(p), d] * W[p, d, e]) * fe[b, j(p), e]
__global__ __launch_bounds__(256, 3) void bilinear_mma_kernel(
    const float* __restrict__ fe,   // fp32, for v_j epilogue
    float* __restrict__ out)
{
    extern __shared__ char smem[];
    const uint32_t base = s2u(smem);
    const int tid   = threadIdx.x;      // 0..255
    const int wid   = tid >> 5;
    const int lid   = tid & 31;
    const int p     = blockIdx.y;       // pair 0..495
    const int btile = blockIdx.x;

    // decode (i, j) from triu_indices(NF, k=1)
    int i = 0, rem = p;
    while (rem >= NF - 1 - i) { rem -= NF - 1 - i; ++i; }
    const int j = i + 1 + rem;

    // ---- async loads (fp16) ----
    // W: 64 rows x 64 fp16 = 512 x 16B chunks, 2/thread
    {
        #pragma unroll
        for (int q = 0; q < 2; ++q) {
            int chunk = tid + 256 * q;                    // 0..511
            int row = chunk >> 3, c = chunk & 7;
            const size_t gb = (size_t)p * DIM * DIM + row * DIM + c * 8;
            cpasync16(base + SM_W + (uint32_t)(row * (LDSTR * 2) + c * 16), g_WF + gb);
        }
    }
    // A: 128 rows x 64 fp16 = 1024 chunks, 4/thread
    {
        #pragma unroll
        for (int q = 0; q < 4; ++q) {
            int chunk = tid + 256 * q;                    // 0..1023
            int row = chunk >> 3, c = chunk & 7;
            const size_t gb = ((size_t)(btile * TILE_M + row) * NF + i) * DIM + c * 8;
            cpasync16(base + SM_A + (uint32_t)(row * (LDSTR * 2) + c * 16), g_feF + gb);
        }
    }
    asm volatile("cp.async.commit_group;" ::: "memory");
    asm volatile("cp.async.wait_group 0;" ::: "memory");
    __syncthreads();

    // ---- warp tile: 32 (m) x 32 (n); 4x2 warp grid (R4 schedule) ----
    const int MR = (wid & 3) * 32;
    const int NC = (wid >> 2) * 32;
    const int lr = lid & 15, lc = lid >> 4;

    const uint32_t aA0 = base + SM_A + (uint32_t)(MR + lr) * (LDSTR * 2) + lc * 16;
    const uint32_t aA1 = aA0 + 16 * (LDSTR * 2);
    const uint32_t aW  = base + SM_W + (uint32_t)lr * (LDSTR * 2) + NC * 2 + lc * 16;

    float acc[2][4][4] = {};

    #pragma unroll
    for (int ks = 0; ks < 4; ++ks) {
        const uint32_t kA = (uint32_t)(ks * 32);               // +16 k-cols (bytes)
        const uint32_t kB = (uint32_t)(ks * 16 * (LDSTR * 2)); // +16 k-rows (bytes)

        uint32_t af[2][4], wf[8];
        ldsm_x4(af[0], aA0 + kA);
        ldsm_x4(af[1], aA1 + kA);
        ldsm_x4t(wf,     aW + kB);
        ldsm_x4t(wf + 4, aW + kB + 32);

        #pragma unroll
        for (int mi = 0; mi < 2; ++mi)
            #pragma unroll
            for (int ni = 0; ni < 4; ++ni)
                mma_f16(acc[mi][ni], af[mi], &wf[ni * 2]);
    }

    // ---- epilogue: PER-WARP bounce (dedicated smem), no CTA barriers ----
    float* bounce = reinterpret_cast<float*>(smem + SM_BNC + wid * BNC_WARP);

    const int r  = lid >> 2;
    const int cp = (lid & 3) * 2;
    #pragma unroll
    for (int mi = 0; mi < 2; ++mi)
        #pragma unroll
        for (int h = 0; h < 2; ++h) {
            const int lrow = mi * 16 + h * 8 + r;              // 0..31 local
            #pragma unroll
            for (int ni = 0; ni < 4; ++ni) {
                const int col = ni * 8 + cp;                   // 0..30 local
                *reinterpret_cast<float2*>(bounce + lrow * BSTR + col) =
                    make_float2(acc[mi][ni][h * 2 + 0], acc[mi][ni][h * 2 + 1]);
            }
        }
    __syncwarp();

    const int lane8 = lid & 7;
    #pragma unroll
    for (int rr = 0; rr < 8; ++rr) {
        const int lrow = rr * 4 + (lid >> 3);                  // 0..31 local
        const int b = btile * TILE_M + MR + lrow;
        const int col = NC + lane8 * 4;
        float4 a4 = *reinterpret_cast<const float4*>(bounce + lrow * BSTR + lane8 * 4);
        float4 vj = *reinterpret_cast<const float4*>(fe + ((size_t)b * NF + j) * DIM + col);
        float4 o;
        o.x = a4.x * vj.x; o.y = a4.y * vj.y;
        o.z = a4.z * vj.z; o.w = a4.w * vj.w;
        *reinterpret_cast<float4*>(out + ((size_t)b * NPAIR + p) * DIM + col) = o;
    }
}

extern "C" void kernel_launch(void* const* d_in, const int* in_sizes, int n_in,
                              void* d_out, int out_size) {
    const float* fe = (const float*)d_in[0];   // feature_emb [2048, 32, 64] fp32
    const float* W  = (const float*)d_in[1];   // bilinear_W [496, 64, 64] fp32
    float* out = (float*)d_out;                // [2048, 496, 64] fp32

    const int n4 = FE4 + NPAIR * DIM * DIM / 4;     // 1556480 float4 total
    cvt_all_kernel<<<(n4 + 255) / 256, 256>>>(fe, W);

    cudaFuncSetAttribute(bilinear_mma_kernel,
                         cudaFuncAttributeMaxDynamicSharedMemorySize, SM_TOTAL);
    dim3 grid(BATCH / TILE_M, NPAIR);          // (16, 496)
    bilinear_mma_kernel<<<grid, 256, SM_TOTAL>>>(fe, out);
}

// round 16
// speedup vs baseline: 1.2205x; 1.0486x over previous
#include <cuda_runtime.h>
#include <cuda_fp16.h>
#include <cstdint>

#define NF 32
#define DIM 64
#define NPAIR 496
#define BATCH 2048
#define TILE_H 64                     // A rows per half-CTA
#define LDSTR 72                      // fp16 elems per smem row (64 + 8 pad)
#define BSTR 40                       // floats per bounce row (validated conflict-free)

// smem: half H at H*18432: A [0,9216), W [9216,18432). Bounce: per-warp 16x40 fp32.
#define HALF_BYTES 18432
#define SM_WOFF 9216
#define SM_BNC 36864
#define BNC_WARP 2560                 // 16 * 40 * 4
#define SM_TOTAL (SM_BNC + 8 * BNC_WARP)   // 57344

#define FE4 (BATCH * NF * DIM / 4)    // 1048576 float4 in fe

// ---- global fp16 scratch (pre-converted) ----
__device__ __align__(16) __half g_feF[BATCH * NF * DIM];
__device__ __align__(16) __half g_WF[NPAIR * DIM * DIM];

__device__ __forceinline__ uint32_t s2u(const void* p) {
    uint32_t a;
    asm("{ .reg .u64 t; cvta.to.shared.u64 t, %1; cvt.u32.u64 %0, t; }" : "=r"(a) : "l"(p));
    return a;
}
__device__ __forceinline__ void cpasync16(uint32_t s, const void* g) {
    asm volatile("{ .reg .u64 gp; cvta.to.global.u64 gp, %1; "
                 "cp.async.ca.shared.global [%0], [gp], 16; }"
                 :: "r"(s), "l"(g) : "memory");
}
__device__ __forceinline__ void ldsm_x4(uint32_t* r, uint32_t a) {
    asm volatile("ldmatrix.sync.aligned.m8n8.x4.shared.b16 {%0,%1,%2,%3}, [%4];"
                 : "=r"(r[0]), "=r"(r[1]), "=r"(r[2]), "=r"(r[3]) : "r"(a));
}
__device__ __forceinline__ void ldsm_x4t(uint32_t* r, uint32_t a) {
    asm volatile("ldmatrix.sync.aligned.m8n8.x4.trans.shared.b16 {%0,%1,%2,%3}, [%4];"
                 : "=r"(r[0]), "=r"(r[1]), "=r"(r[2]), "=r"(r[3]) : "r"(a));
}
__device__ __forceinline__ void mma_f16(float* d, const uint32_t* a, const uint32_t* b) {
    asm volatile("mma.sync.aligned.m16n8k16.row.col.f32.f16.f16.f32 "
                 "{%0,%1,%2,%3}, {%4,%5,%6,%7}, {%8,%9}, {%0,%1,%2,%3};"
                 : "+f"(d[0]), "+f"(d[1]), "+f"(d[2]), "+f"(d[3])
                 : "r"(a[0]), "r"(a[1]), "r"(a[2]), "r"(a[3]), "r"(b[0]), "r"(b[1]));
}

// ---- fused prep kernel: fp32 -> fp16 ----
__global__ __launch_bounds__(256) void cvt_all_kernel(
    const float* __restrict__ fe, const float* __restrict__ W) {
    int idx = blockIdx.x * 256 + threadIdx.x;
    float4 v;
    __half2* dst;
    if (idx < FE4) {
        v = reinterpret_cast<const float4*>(fe)[idx];
        dst = reinterpret_cast<__half2*>(g_feF) + idx * 2;
    } else {
        v = reinterpret_cast<const float4*>(W)[idx - FE4];
        dst = reinterpret_cast<__half2*>(g_WF) + (idx - FE4) * 2;
    }
    dst[0] = __floats2half2_rn(v.x, v.y);
    dst[1] = __floats2half2_rn(v.z, v.w);
}

// out[b, p, e] = (sum_d fe[b, i(p), d] * W[p, d, e]) * fe[b, j(p), e]
__global__ __launch_bounds__(256, 3) void bilinear_mma_kernel(
    const float* __restrict__ fe,   // fp32, for v_j epilogue
    float* __restrict__ out)
{
    extern __shared__ char smem[];
    const uint32_t base = s2u(smem);
    const int tid   = threadIdx.x;      // 0..255
    const int H     = tid >> 7;         // half 0/1
    const int htid  = tid & 127;
    const int hwid  = htid >> 5;        // 0..3 within half
    const int wid   = tid >> 5;         // 0..7 global
    const int lid   = tid & 31;
    const int p     = blockIdx.y;       // pair 0..495
    const int btile = blockIdx.x * 2 + H;   // 64-row tile index, 0..31

    // decode (i, j) from triu_indices(NF, k=1)
    int i = 0, rem = p;
    while (rem >= NF - 1 - i) { rem -= NF - 1 - i; ++i; }
    const int j = i + 1 + rem;

    const uint32_t hbase = base + (uint32_t)(H * HALF_BYTES);

    // ---- async loads (per half; fully independent) ----
    // W: 64 rows x 64 fp16 = 512 x 16B chunks, 4/half-thread
    {
        #pragma unroll
        for (int q = 0; q < 4; ++q) {
            int chunk = htid + 128 * q;                   // 0..511
            int row = chunk >> 3, c = chunk & 7;
            const size_t gb = (size_t)p * DIM * DIM + row * DIM + c * 8;
            cpasync16(hbase + SM_WOFF + (uint32_t)(row * (LDSTR * 2) + c * 16), g_WF + gb);
        }
    }
    // A: 64 rows x 64 fp16 = 512 chunks, 4/half-thread
    {
        #pragma unroll
        for (int q = 0; q < 4; ++q) {
            int chunk = htid + 128 * q;                   // 0..511
            int row = chunk >> 3, c = chunk & 7;
            const size_t gb = ((size_t)(btile * TILE_H + row) * NF + i) * DIM + c * 8;
            cpasync16(hbase + (uint32_t)(row * (LDSTR * 2) + c * 16), g_feF + gb);
        }
    }
    asm volatile("cp.async.commit_group;" ::: "memory");
    asm volatile("cp.async.wait_group 0;" ::: "memory");
    // half-scoped barrier: only this half's 128 threads
    asm volatile("bar.sync %0, 128;" :: "r"(1 + H) : "memory");

    // ---- warp tile: 32 (m) x 32 (n); 2x2 warp grid per half ----
    const int MR = (hwid & 1) * 32;
    const int NC = (hwid >> 1) * 32;
    const int lr = lid & 15, lc = lid >> 4;

    const uint32_t aA0 = hbase + (uint32_t)(MR + lr) * (LDSTR * 2) + lc * 16;
    const uint32_t aA1 = aA0 + 16 * (LDSTR * 2);
    const uint32_t aW  = hbase + SM_WOFF + (uint32_t)lr * (LDSTR * 2) + NC * 2 + lc * 16;

    float acc[2][4][4] = {};

    #pragma unroll
    for (int ks = 0; ks < 4; ++ks) {
        const uint32_t kA = (uint32_t)(ks * 32);               // +16 k-cols (bytes)
        const uint32_t kB = (uint32_t)(ks * 16 * (LDSTR * 2)); // +16 k-rows (bytes)

        uint32_t af[2][4], wf[8];
        ldsm_x4(af[0], aA0 + kA);
        ldsm_x4(af[1], aA1 + kA);
        ldsm_x4t(wf,     aW + kB);
        ldsm_x4t(wf + 4, aW + kB + 32);

        #pragma unroll
        for (int mi = 0; mi < 2; ++mi)
            #pragma unroll
            for (int ni = 0; ni < 4; ++ni)
                mma_f16(acc[mi][ni], af[mi], &wf[ni * 2]);
    }

    // ---- epilogue: per-warp 16-row bounce, two rounds, warp-local sync only ----
    float* bounce = reinterpret_cast<float*>(smem + SM_BNC + wid * BNC_WARP);
    const int r     = lid >> 2;
    const int cp    = (lid & 3) * 2;
    const int lane8 = lid & 7;

    #pragma unroll
    for (int mi = 0; mi < 2; ++mi) {
        #pragma unroll
        for (int h = 0; h < 2; ++h) {
            const int lrow = h * 8 + r;                        // 0..15
            #pragma unroll
            for (int ni = 0; ni < 4; ++ni) {
                const int col = ni * 8 + cp;
                *reinterpret_cast<float2*>(bounce + lrow * BSTR + col) =
                    make_float2(acc[mi][ni][h * 2 + 0], acc[mi][ni][h * 2 + 1]);
            }
        }
        __syncwarp();
        #pragma unroll
        for (int rr = 0; rr < 4; ++rr) {
            const int lrow = rr * 4 + (lid >> 3);              // 0..15
            const int b = btile * TILE_H + MR + mi * 16 + lrow;
            const int col = NC + lane8 * 4;
            float4 a4 = *reinterpret_cast<const float4*>(bounce + lrow * BSTR + lane8 * 4);
            float4 vj = *reinterpret_cast<const float4*>(fe + ((size_t)b * NF + j) * DIM + col);
            float4 o;
            o.x = a4.x * vj.x; o.y = a4.y * vj.y;
            o.z = a4.z * vj.z; o.w = a4.w * vj.w;
            *reinterpret_cast<float4*>(out + ((size_t)b * NPAIR + p) * DIM + col) = o;
        }
        __syncwarp();
    }
}

extern "C" void kernel_launch(void* const* d_in, const int* in_sizes, int n_in,
                              void* d_out, int out_size) {
    const float* fe = (const float*)d_in[0];   // feature_emb [2048, 32, 64] fp32
    const float* W  = (const float*)d_in[1];   // bilinear_W [496, 64, 64] fp32
    float* out = (float*)d_out;                // [2048, 496, 64] fp32

    const int n4 = FE4 + NPAIR * DIM * DIM / 4;     // 1556480 float4 total
    cvt_all_kernel<<<(n4 + 255) / 256, 256>>>(fe, W);

    cudaFuncSetAttribute(bilinear_mma_kernel,
                         cudaFuncAttributeMaxDynamicSharedMemorySize, SM_TOTAL);
    dim3 grid(BATCH / (2 * TILE_H), NPAIR);    // (16, 496)
    bilinear_mma_kernel<<<grid, 256, SM_TOTAL>>>(fe, out);
}